// round 4
// baseline (speedup 1.0000x reference)
#include <cuda_runtime.h>
#include <math.h>

#define BSZ       512
#define NODES     1000
#define DIM       128
#define NB_HEADS  8
#define EMB3      384          // DIM * 3 layers, row stride of K_att / V_att
#define LSTR      1001         // smem stride

// Intermediate query buffers (device scratch; allocation-free per harness rules)
__device__ float g_q[2][BSZ * DIM];

// ---------------------------------------------------------------------------
// Decode mask row for batch b into smask[0..NODES) with runtime layout
// detection (uint8 / int32 / float32), voted once per block.
// ---------------------------------------------------------------------------
__device__ __forceinline__ void load_mask_row(const void* mask, int b, int tid,
                                              unsigned char* smask)
{
    const unsigned char* p = (const unsigned char*)mask;
    bool viol_i32 = false, viol_f32 = false;
    if (tid < 256) {
        unsigned char b0 = p[4 * tid + 0];
        unsigned char b1 = p[4 * tid + 1];
        unsigned char b2 = p[4 * tid + 2];
        unsigned char b3 = p[4 * tid + 3];
        viol_i32 = (b1 | b2 | b3) != 0;
        bool zero = (b0 | b1 | b2 | b3) == 0;
        bool one  = (b0 == 0 && b1 == 0 && b2 == 0x80 && b3 == 0x3f);
        viol_f32 = !(zero || one);
    }
    const int any_i32_viol = __syncthreads_or(viol_i32);
    const int any_f32_viol = __syncthreads_or(viol_f32);

    if (!any_i32_viol) {
        const int* mi = (const int*)mask + (size_t)b * NODES;
        for (int n = tid; n < NODES; n += blockDim.x) smask[n] = (mi[n] != 0);
    } else if (!any_f32_viol) {
        const float* mf = (const float*)mask + (size_t)b * NODES;
        for (int n = tid; n < NODES; n += blockDim.x) smask[n] = (mf[n] != 0.0f);
    } else {
        const unsigned char* mu = (const unsigned char*)mask + (size_t)b * NODES;
        for (int n = tid; n < NODES; n += blockDim.x) smask[n] = (mu[n] != 0);
    }
    __syncthreads();
}

// ---------------------------------------------------------------------------
// Layers 0 and 1: 8-head MHA + fused 128x128 linear (W0).
// ONLINE softmax (no max-subtraction; logits are O(5), exp cannot overflow,
// softmax is shift-invariant). K and V streams fully fused: per node, the
// owning warp computes the head dot, e = exp(logit) (0 if masked), and
// accumulates e * V_row and the denominator in registers. Zero softmax
// barriers; 4 loads in flight per warp.
// ---------------------------------------------------------------------------
__global__ __launch_bounds__(512, 4)
void attn_layer01(const float* __restrict__ K_att,
                  const float* __restrict__ V_att,
                  const void*  __restrict__ mask,
                  const float* __restrict__ query0,
                  const float* __restrict__ W0w,
                  const float* __restrict__ W0b,
                  int layer)
{
    __shared__ __align__(16) float sq[DIM];
    __shared__ __align__(16) float spart[16][DIM];  // per-warp e*V partials (8 KB)
    __shared__ float ssum[16][NB_HEADS];            // per-warp e sums per head
    __shared__ float sinv[NB_HEADS];
    __shared__ float sout[DIM];
    __shared__ unsigned char smask[NODES];

    const int b    = blockIdx.x;
    const int tid  = threadIdx.x;
    const int lane = tid & 31;
    const int warp = tid >> 5;

    load_mask_row(mask, b, tid, smask);

    const float* qin = (layer == 0) ? (query0 + b * DIM) : (g_q[0] + b * DIM);
    if (tid < DIM) sq[tid] = qin[tid];
    __syncthreads();

    const float4 q4 = reinterpret_cast<const float4*>(sq)[lane];
    const float* Kb = K_att + (size_t)b * NODES * EMB3 + layer * DIM;
    const float* Vb = V_att + (size_t)b * NODES * EMB3 + layer * DIM;

    float4 acc = make_float4(0.f, 0.f, 0.f, 0.f);
    float  es  = 0.f;

    // Fused K+V online loop: 2 nodes per iter, 4 outstanding 16B loads.
    for (int n0 = warp * 2; n0 < NODES; n0 += 32) {
        const float4 k0 = __ldg(reinterpret_cast<const float4*>(Kb + (size_t)n0 * EMB3) + lane);
        const float4 v0 = __ldg(reinterpret_cast<const float4*>(Vb + (size_t)n0 * EMB3) + lane);
        const float4 k1 = __ldg(reinterpret_cast<const float4*>(Kb + (size_t)(n0 + 1) * EMB3) + lane);
        const float4 v1 = __ldg(reinterpret_cast<const float4*>(Vb + (size_t)(n0 + 1) * EMB3) + lane);

        // node n0
        {
            float p = k0.x * q4.x + k0.y * q4.y + k0.z * q4.z + k0.w * q4.w;
            p += __shfl_xor_sync(0xffffffffu, p, 1);
            p += __shfl_xor_sync(0xffffffffu, p, 2);
            float e = smask[n0] ? 0.f : __expf(p * 0.25f);   // 1/sqrt(16)
            es += e;
            acc.x += e * v0.x; acc.y += e * v0.y; acc.z += e * v0.z; acc.w += e * v0.w;
        }
        // node n0+1
        {
            float p = k1.x * q4.x + k1.y * q4.y + k1.z * q4.z + k1.w * q4.w;
            p += __shfl_xor_sync(0xffffffffu, p, 1);
            p += __shfl_xor_sync(0xffffffffu, p, 2);
            float e = smask[n0 + 1] ? 0.f : __expf(p * 0.25f);
            es += e;
            acc.x += e * v1.x; acc.y += e * v1.y; acc.z += e * v1.z; acc.w += e * v1.w;
        }
    }

    reinterpret_cast<float4*>(spart[warp])[lane] = acc;
    if ((lane & 3) == 0) ssum[warp][lane >> 2] = es;
    __syncthreads();

    if (tid < NB_HEADS) {
        float s = 0.f;
        #pragma unroll
        for (int w = 0; w < 16; w++) s += ssum[w][tid];
        sinv[tid] = 1.0f / s;
    }
    __syncthreads();

    if (tid < DIM) {
        float r = 0.f;
        #pragma unroll
        for (int w = 0; w < 16; w++) r += spart[w][tid];
        sout[tid] = r * sinv[tid >> 4];
    }
    __syncthreads();

    // Fused linear: q_next = out @ W0w^T + W0b
    if (tid < DIM) {
        float r = W0b[tid];
        const float* Wr = W0w + tid * DIM;
        #pragma unroll 8
        for (int k = 0; k < DIM; k++) r += Wr[k] * sout[k];
        g_q[layer][b * DIM + tid] = r;
    }
}

// ---------------------------------------------------------------------------
// Final layer: q = Wq q + b ; single-head logits with 10*tanh clip, mask,
// softmax over 1000 nodes -> output probabilities (512, 1000).
// Clip bounds logits to [-10,10] -> exp without max-subtraction is safe.
// ---------------------------------------------------------------------------
__global__ __launch_bounds__(512, 4)
void attn_final(const float* __restrict__ K_att,
                const void*  __restrict__ mask,
                const float* __restrict__ Wqw,
                const float* __restrict__ Wqb,
                float* __restrict__ out)
{
    __shared__ __align__(16) float sqin[DIM];
    __shared__ __align__(16) float sq[DIM];
    __shared__ float spartl[8 * LSTR];   // per-16-dim-group logit partials (32 KB)
    __shared__ float sexp[NODES];
    __shared__ float sreds[16];
    __shared__ unsigned char smask[NODES];

    const int b    = blockIdx.x;
    const int tid  = threadIdx.x;
    const int lane = tid & 31;
    const int warp = tid >> 5;

    load_mask_row(mask, b, tid, smask);

    if (tid < DIM) sqin[tid] = g_q[1][b * DIM + tid];
    __syncthreads();
    if (tid < DIM) {
        float r = Wqb[tid];
        const float* Wr = Wqw + tid * DIM;
        #pragma unroll 8
        for (int k = 0; k < DIM; k++) r += Wr[k] * sqin[k];
        sq[tid] = r;
    }
    __syncthreads();

    const float4 q4 = reinterpret_cast<const float4*>(sq)[lane];
    const float* Kb = K_att + (size_t)b * NODES * EMB3 + 2 * DIM;

    // Hot loop: K stream, 4 nodes per iter, 2-shuffle partials.
    for (int n0 = warp * 4; n0 < NODES; n0 += 64) {
        float4 k[4];
        #pragma unroll
        for (int i = 0; i < 4; i++)
            k[i] = __ldg(reinterpret_cast<const float4*>(Kb + (size_t)(n0 + i) * EMB3) + lane);
        #pragma unroll
        for (int i = 0; i < 4; i++) {
            float p = k[i].x * q4.x + k[i].y * q4.y + k[i].z * q4.z + k[i].w * q4.w;
            p += __shfl_xor_sync(0xffffffffu, p, 1);
            p += __shfl_xor_sync(0xffffffffu, p, 2);
            if ((lane & 3) == 0) spartl[(lane >> 2) * LSTR + (n0 + i)] = p;
        }
    }
    __syncthreads();

    // Combine partials -> exp(clip(logit)) (no max pass needed; |lg| <= 10)
    const float scale = 0.0883883476483184f;   // 1/sqrt(128)
    float s = 0.f;
    for (int n = tid; n < NODES; n += 512) {
        float d = 0.f;
        #pragma unroll
        for (int h = 0; h < 8; h++) d += spartl[h * LSTR + n];
        float e = smask[n] ? 0.f : __expf(10.0f * tanhf(d * scale));
        sexp[n] = e;
        s += e;
    }
    #pragma unroll
    for (int o = 16; o; o >>= 1) s += __shfl_xor_sync(0xffffffffu, s, o);
    if (lane == 0) sreds[warp] = s;
    __syncthreads();
    if (tid < 32) {
        float ss = (lane < 16) ? sreds[lane] : 0.f;
        #pragma unroll
        for (int o = 8; o; o >>= 1) ss += __shfl_xor_sync(0xffffffffu, ss, o);
        if (lane == 0) sreds[0] = ss;
    }
    __syncthreads();
    const float inv = 1.0f / sreds[0];

    float* ob = out + (size_t)b * NODES;
    for (int n = tid; n < NODES; n += 512) ob[n] = sexp[n] * inv;
}

// ---------------------------------------------------------------------------
extern "C" void kernel_launch(void* const* d_in, const int* in_sizes, int n_in,
                              void* d_out, int out_size)
{
    const float* query = (const float*)d_in[0];
    const float* K_att = (const float*)d_in[1];
    const float* V_att = (const float*)d_in[2];
    const void*  mask  = d_in[3];
    const float* W0w   = (const float*)d_in[4];
    const float* W0b   = (const float*)d_in[5];
    const float* Wqw   = (const float*)d_in[6];
    const float* Wqb   = (const float*)d_in[7];
    float* out = (float*)d_out;

    attn_layer01<<<BSZ, 512>>>(K_att, V_att, mask, query, W0w, W0b, 0);
    attn_layer01<<<BSZ, 512>>>(K_att, V_att, mask, query, W0w, W0b, 1);
    attn_final  <<<BSZ, 512>>>(K_att, mask, Wqw, Wqb, out);
}

// round 5
// speedup vs baseline: 1.0719x; 1.0719x over previous
#include <cuda_runtime.h>
#include <math.h>

#define BSZ       512
#define NODES     1000
#define DIM       128
#define NB_HEADS  8
#define EMB3      384          // DIM * 3 layers, row stride of K_att / V_att
#define LSTR      1001         // smem stride -> conflict-free per-head access

// Intermediate query buffers (device scratch; allocation-free per harness rules)
__device__ float g_q[2][BSZ * DIM];

// ---------------------------------------------------------------------------
// Decode mask row for batch b into smask[0..NODES) with runtime layout
// detection (uint8 / int32 / float32), voted once per block.
// ---------------------------------------------------------------------------
__device__ __forceinline__ void load_mask_row(const void* mask, int b, int tid,
                                              unsigned char* smask)
{
    const unsigned char* p = (const unsigned char*)mask;
    bool viol_i32 = false, viol_f32 = false;
    if (tid < 256) {
        unsigned char b0 = p[4 * tid + 0];
        unsigned char b1 = p[4 * tid + 1];
        unsigned char b2 = p[4 * tid + 2];
        unsigned char b3 = p[4 * tid + 3];
        viol_i32 = (b1 | b2 | b3) != 0;
        bool zero = (b0 | b1 | b2 | b3) == 0;
        bool one  = (b0 == 0 && b1 == 0 && b2 == 0x80 && b3 == 0x3f);
        viol_f32 = !(zero || one);
    }
    const int any_i32_viol = __syncthreads_or(viol_i32);
    const int any_f32_viol = __syncthreads_or(viol_f32);

    if (!any_i32_viol) {
        const int* mi = (const int*)mask + (size_t)b * NODES;
        for (int n = tid; n < NODES; n += blockDim.x) smask[n] = (mi[n] != 0);
    } else if (!any_f32_viol) {
        const float* mf = (const float*)mask + (size_t)b * NODES;
        for (int n = tid; n < NODES; n += blockDim.x) smask[n] = (mf[n] != 0.0f);
    } else {
        const unsigned char* mu = (const unsigned char*)mask + (size_t)b * NODES;
        for (int n = tid; n < NODES; n += blockDim.x) smask[n] = (mu[n] != 0);
    }
    __syncthreads();
}

// ---------------------------------------------------------------------------
// Layers 0 and 1: 8-head MHA + fused 128x128 linear (W0).
// Phase A streams K (4 nodes/iter, 4 loads in flight), computes
// e = exp(logit) directly (no max pass; logits O(5), shift-invariant),
// stores e to slog and accumulates per-head denominators in registers.
// Phase B streams V (4 nodes/iter) weighting by e. One block per batch row.
// ---------------------------------------------------------------------------
__global__ __launch_bounds__(512, 4)
void attn_layer01(const float* __restrict__ K_att,
                  const float* __restrict__ V_att,
                  const void*  __restrict__ mask,
                  const float* __restrict__ query0,
                  const float* __restrict__ W0w,
                  const float* __restrict__ W0b,
                  int layer)
{
    __shared__ __align__(16) float sq[DIM];
    __shared__ float slog[NB_HEADS * LSTR];         // exp weights (32 KB)
    __shared__ float ssum[16][NB_HEADS];            // per-warp denominators
    __shared__ float sinv[NB_HEADS];
    __shared__ __align__(16) float spart[16][DIM];  // per-warp e*V partials (8 KB)
    __shared__ float sout[DIM];
    __shared__ unsigned char smask[NODES];

    const int b    = blockIdx.x;
    const int tid  = threadIdx.x;
    const int lane = tid & 31;
    const int warp = tid >> 5;

    load_mask_row(mask, b, tid, smask);

    const float* qin = (layer == 0) ? (query0 + b * DIM) : (g_q[0] + b * DIM);
    if (tid < DIM) sq[tid] = qin[tid];
    __syncthreads();

    const float4 q4 = reinterpret_cast<const float4*>(sq)[lane];
    const float* Kb = K_att + (size_t)b * NODES * EMB3 + layer * DIM;
    const float* Vb = V_att + (size_t)b * NODES * EMB3 + layer * DIM;

    // ---- Phase A: K stream -> e weights + per-head partial denominators ---
    {
        float es = 0.f;                 // valid on lanes with (lane&3)==0
        for (int n0 = warp * 4; n0 < NODES; n0 += 64) {
            float4 k[4];
            #pragma unroll
            for (int i = 0; i < 4; i++)
                k[i] = __ldg(reinterpret_cast<const float4*>(Kb + (size_t)(n0 + i) * EMB3) + lane);
            #pragma unroll
            for (int i = 0; i < 4; i++) {
                float p = k[i].x * q4.x + k[i].y * q4.y + k[i].z * q4.z + k[i].w * q4.w;
                p += __shfl_xor_sync(0xffffffffu, p, 1);
                p += __shfl_xor_sync(0xffffffffu, p, 2);
                if ((lane & 3) == 0) {
                    const int n = n0 + i;
                    float e = smask[n] ? 0.f : __expf(p * 0.25f);   // 1/sqrt(16)
                    slog[(lane >> 2) * LSTR + n] = e;
                    es += e;
                }
            }
        }
        if ((lane & 3) == 0) ssum[warp][lane >> 2] = es;
    }
    __syncthreads();

    if (tid < NB_HEADS) {
        float s = 0.f;
        #pragma unroll
        for (int w = 0; w < 16; w++) s += ssum[w][tid];
        sinv[tid] = 1.0f / s;
    }

    // ---- Phase B: V stream, warp-per-node, 4 loads in flight ---------------
    {
        const float* Lh = slog + (lane >> 2) * LSTR;
        float4 acc = make_float4(0.f, 0.f, 0.f, 0.f);
        int n = warp;
        for (; n + 48 < NODES; n += 64) {
            float4 v[4];
            #pragma unroll
            for (int i = 0; i < 4; i++)
                v[i] = __ldg(reinterpret_cast<const float4*>(Vb + (size_t)(n + 16 * i) * EMB3) + lane);
            #pragma unroll
            for (int i = 0; i < 4; i++) {
                const float w = Lh[n + 16 * i];
                acc.x += w * v[i].x; acc.y += w * v[i].y;
                acc.z += w * v[i].z; acc.w += w * v[i].w;
            }
        }
        for (; n < NODES; n += 16) {
            float4 v0 = __ldg(reinterpret_cast<const float4*>(Vb + (size_t)n * EMB3) + lane);
            const float w = Lh[n];
            acc.x += w * v0.x; acc.y += w * v0.y; acc.z += w * v0.z; acc.w += w * v0.w;
        }
        reinterpret_cast<float4*>(spart[warp])[lane] = acc;
    }
    __syncthreads();

    if (tid < DIM) {
        float r = 0.f;
        #pragma unroll
        for (int w = 0; w < 16; w++) r += spart[w][tid];
        sout[tid] = r * sinv[tid >> 4];
    }
    __syncthreads();

    // ---- Fused linear: q_next = out @ W0w^T + W0b --------------------------
    if (tid < DIM) {
        float r = W0b[tid];
        const float* Wr = W0w + tid * DIM;
        #pragma unroll 8
        for (int k = 0; k < DIM; k++) r += Wr[k] * sout[k];
        g_q[layer][b * DIM + tid] = r;
    }
}

// ---------------------------------------------------------------------------
// Final layer: q = Wq q + b ; single-head logits with 10*tanh clip, mask,
// softmax over 1000 nodes -> output probabilities (512, 1000).
// Clip bounds logits to [-10,10] -> exp without max-subtraction is safe.
// ---------------------------------------------------------------------------
__global__ __launch_bounds__(512, 4)
void attn_final(const float* __restrict__ K_att,
                const void*  __restrict__ mask,
                const float* __restrict__ Wqw,
                const float* __restrict__ Wqb,
                float* __restrict__ out)
{
    __shared__ __align__(16) float sqin[DIM];
    __shared__ __align__(16) float sq[DIM];
    __shared__ float spartl[8 * LSTR];   // per-16-dim-group logit partials (32 KB)
    __shared__ float sexp[NODES];
    __shared__ float sreds[16];
    __shared__ unsigned char smask[NODES];

    const int b    = blockIdx.x;
    const int tid  = threadIdx.x;
    const int lane = tid & 31;
    const int warp = tid >> 5;

    load_mask_row(mask, b, tid, smask);

    if (tid < DIM) sqin[tid] = g_q[1][b * DIM + tid];
    __syncthreads();
    if (tid < DIM) {
        float r = Wqb[tid];
        const float* Wr = Wqw + tid * DIM;
        #pragma unroll 8
        for (int k = 0; k < DIM; k++) r += Wr[k] * sqin[k];
        sq[tid] = r;
    }
    __syncthreads();

    const float4 q4 = reinterpret_cast<const float4*>(sq)[lane];
    const float* Kb = K_att + (size_t)b * NODES * EMB3 + 2 * DIM;

    // Hot loop: K stream, 4 nodes per iter, 2-shuffle partials.
    for (int n0 = warp * 4; n0 < NODES; n0 += 64) {
        float4 k[4];
        #pragma unroll
        for (int i = 0; i < 4; i++)
            k[i] = __ldg(reinterpret_cast<const float4*>(Kb + (size_t)(n0 + i) * EMB3) + lane);
        #pragma unroll
        for (int i = 0; i < 4; i++) {
            float p = k[i].x * q4.x + k[i].y * q4.y + k[i].z * q4.z + k[i].w * q4.w;
            p += __shfl_xor_sync(0xffffffffu, p, 1);
            p += __shfl_xor_sync(0xffffffffu, p, 2);
            if ((lane & 3) == 0) spartl[(lane >> 2) * LSTR + (n0 + i)] = p;
        }
    }
    __syncthreads();

    // Combine partials -> exp(clip(logit)) (no max pass needed; |lg| <= 10)
    const float scale = 0.0883883476483184f;   // 1/sqrt(128)
    float s = 0.f;
    for (int n = tid; n < NODES; n += 512) {
        float d = 0.f;
        #pragma unroll
        for (int h = 0; h < 8; h++) d += spartl[h * LSTR + n];
        float e = smask[n] ? 0.f : __expf(10.0f * tanhf(d * scale));
        sexp[n] = e;
        s += e;
    }
    #pragma unroll
    for (int o = 16; o; o >>= 1) s += __shfl_xor_sync(0xffffffffu, s, o);
    if (lane == 0) sreds[warp] = s;
    __syncthreads();
    if (tid < 32) {
        float ss = (lane < 16) ? sreds[lane] : 0.f;
        #pragma unroll
        for (int o = 8; o; o >>= 1) ss += __shfl_xor_sync(0xffffffffu, ss, o);
        if (lane == 0) sreds[0] = ss;
    }
    __syncthreads();
    const float inv = 1.0f / sreds[0];

    float* ob = out + (size_t)b * NODES;
    for (int n = tid; n < NODES; n += 512) ob[n] = sexp[n] * inv;
}

// ---------------------------------------------------------------------------
extern "C" void kernel_launch(void* const* d_in, const int* in_sizes, int n_in,
                              void* d_out, int out_size)
{
    const float* query = (const float*)d_in[0];
    const float* K_att = (const float*)d_in[1];
    const float* V_att = (const float*)d_in[2];
    const void*  mask  = d_in[3];
    const float* W0w   = (const float*)d_in[4];
    const float* W0b   = (const float*)d_in[5];
    const float* Wqw   = (const float*)d_in[6];
    const float* Wqb   = (const float*)d_in[7];
    float* out = (float*)d_out;

    attn_layer01<<<BSZ, 512>>>(K_att, V_att, mask, query, W0w, W0b, 0);
    attn_layer01<<<BSZ, 512>>>(K_att, V_att, mask, query, W0w, W0b, 1);
    attn_final  <<<BSZ, 512>>>(K_att, mask, Wqw, Wqb, out);
}